// round 11
// baseline (speedup 1.0000x reference)
#include <cuda_runtime.h>
#include <cstdint>

// out[r] = sum_{e: row[e]==r} val[e] * embs[col[e]]
// E = 3.2M, N = 100K, D = 128, fp32.
//
// Warp handles 32 edges: lane-coalesced index load, shfl broadcast, then
// chunked processing: 8 independent 512B gathers (MLP ~8 on L2-resident
// embs), then 8 red.global.add.v4.f32 scatters (no-return reduction, 4x
// fewer L2 atomic ops than scalar, no scoreboard wait, no memory clobber
// so later gathers can hoist above them). embs (51MB) + out (51MB) fit L2.

#define CHUNK 8

__global__ void __launch_bounds__(256)
gcn_spmm_kernel(const int* __restrict__ edge_row,
                const int* __restrict__ edge_col,
                const float* __restrict__ edge_val,
                const float4* __restrict__ embs4,   // [N, 32] float4
                float4* __restrict__ out4,          // [N, 32] float4
                int n_edges)
{
    const int lane = threadIdx.x & 31;
    const int warp_id = (blockIdx.x * blockDim.x + threadIdx.x) >> 5;
    const int base = warp_id * 32;
    if (base >= n_edges) return;

    // Coalesced load of this warp's 32 edges
    int r = 0, c = 0;
    float v = 0.0f;
    const int e = base + lane;
    if (e < n_edges) {
        r = edge_row[e];
        c = edge_col[e];
        v = edge_val[e];
    }

    if (base + 32 <= n_edges) {
        // Hot path: full 32-edge group, 4 chunks of 8, no tail logic.
        #pragma unroll
        for (int j = 0; j < 32; j += CHUNK) {
            int   rj[CHUNK], cj[CHUNK];
            float vj[CHUNK];
            #pragma unroll
            for (int k = 0; k < CHUNK; k++) {
                rj[k] = __shfl_sync(0xffffffffu, r, j + k);
                cj[k] = __shfl_sync(0xffffffffu, c, j + k);
                vj[k] = __shfl_sync(0xffffffffu, v, j + k);
            }

            // 8 independent 512B gathers -> high MLP on L2-resident table.
            float4 m[CHUNK];
            #pragma unroll
            for (int k = 0; k < CHUNK; k++)
                m[k] = __ldg(&embs4[(size_t)cj[k] * 32 + lane]);

            #pragma unroll
            for (int k = 0; k < CHUNK; k++) {
                m[k].x *= vj[k]; m[k].y *= vj[k];
                m[k].z *= vj[k]; m[k].w *= vj[k];
            }

            // Fire-and-forget vectorized reductions.
            #pragma unroll
            for (int k = 0; k < CHUNK; k++) {
                float4* dst = out4 + (size_t)rj[k] * 32 + lane;
                asm volatile("red.global.add.v4.f32 [%0], {%1,%2,%3,%4};"
                             :: "l"(dst),
                                "f"(m[k].x), "f"(m[k].y),
                                "f"(m[k].z), "f"(m[k].w));
            }
        }
    } else {
        // Tail: final partial group of the grid.
        const int cnt = n_edges - base;
        for (int j = 0; j < cnt; j++) {
            const int   rj = __shfl_sync(0xffffffffu, r, j);
            const int   cj = __shfl_sync(0xffffffffu, c, j);
            const float vj = __shfl_sync(0xffffffffu, v, j);
            float4 m = __ldg(&embs4[(size_t)cj * 32 + lane]);
            m.x *= vj; m.y *= vj; m.z *= vj; m.w *= vj;
            float4* dst = out4 + (size_t)rj * 32 + lane;
            asm volatile("red.global.add.v4.f32 [%0], {%1,%2,%3,%4};"
                         :: "l"(dst), "f"(m.x), "f"(m.y), "f"(m.z), "f"(m.w));
        }
    }
}

extern "C" void kernel_launch(void* const* d_in, const int* in_sizes, int n_in,
                              void* d_out, int out_size)
{
    const int*    edge_row = (const int*)   d_in[0];
    const int*    edge_col = (const int*)   d_in[1];
    const float*  edge_val = (const float*) d_in[2];
    const float4* embs4    = (const float4*)d_in[3];
    // d_in[4] = n_nodes scalar (unused; out_size/128 gives it)

    const int n_edges = in_sizes[0];
    float4* out4 = (float4*)d_out;

    // Output is poisoned; zero it (graph-capturable memset node).
    cudaMemsetAsync(d_out, 0, (size_t)out_size * sizeof(float), 0);

    // One warp per 32 edges
    const int warps_needed = (n_edges + 31) / 32;
    const int threads = 256;                       // 8 warps/block
    const int blocks = (warps_needed + 7) / 8;

    gcn_spmm_kernel<<<blocks, threads>>>(edge_row, edge_col, edge_val,
                                         embs4, out4, n_edges);
}